// round 14
// baseline (speedup 1.0000x reference)
#include <cuda_runtime.h>
#include <cuda_fp16.h>

#define NT  262144          /* B*H*S rows per tensor */
#define QS  136             /* smem row stride in halves */

__device__ __align__(16) float  g_P[2][16384];   /* 32-reflector partial products */
__device__ __align__(16) __half g_Qhi[16384];    /* em/dm-permuted Q */

// ---------------------------------------------------------------------------
// Stage 1: two parallel 32-reflector partial products.
// ---------------------------------------------------------------------------
__global__ void build_p_kernel(const float* __restrict__ vs)
{
    __shared__ float svs[32 * 128];
    __shared__ float sinv[32];
    const int t = threadIdx.x;
    const int chunk = blockIdx.x >> 4;
    const float* vsrc = vs + chunk * 32 * 128;
    for (int i = t; i < 32 * 128; i += 128) svs[i] = vsrc[i];
    __syncthreads();
    if (t < 32) {
        float nn = 0.f;
#pragma unroll 8
        for (int i = 0; i < 128; i += 4) {
            const float4 v = *(const float4*)&svs[t * 128 + i];
            nn += v.x * v.x + v.y * v.y + v.z * v.z + v.w * v.w;
        }
        sinv[t] = 2.0f / (nn + 1e-8f);
    }
    __syncthreads();

    const int col = (blockIdx.x & 15) * 8 + (t >> 4);
    const int ip  = t & 15;
    float qc[8];
#pragma unroll
    for (int j = 0; j < 8; j++) qc[j] = (ip * 8 + j == col) ? 1.0f : 0.0f;

    for (int r = 0; r < 32; r++) {
        const float* v = &svs[r * 128 + ip * 8];
        float w = 0.f;
#pragma unroll
        for (int j = 0; j < 8; j++) w += v[j] * qc[j];
#pragma unroll
        for (int off = 8; off; off >>= 1) w += __shfl_xor_sync(0xffffffffu, w, off);
        const float sw = sinv[r] * w;
#pragma unroll
        for (int j = 0; j < 8; j++) qc[j] -= sw * v[j];
    }
#pragma unroll
    for (int j = 0; j < 8; j++) g_P[chunk][(ip * 8 + j) * 128 + col] = qc[j];
}

// ---------------------------------------------------------------------------
// Stage 2: Q = P1 * P0 -> fp16, both dims within-16 permuted.
// ---------------------------------------------------------------------------
__global__ void combine_q_kernel()
{
    __shared__ float rowa[128];
    const int i = blockIdx.x, j = threadIdx.x;
    rowa[j] = g_P[1][i * 128 + j];
    __syncthreads();
    float s = 0.f;
#pragma unroll 8
    for (int e = 0; e < 128; e++) s += rowa[e] * g_P[0][e * 128 + j];
    const int mi = (i & ~15) | (((i >> 1) & 1) << 3) | (((i & 15) >> 2) << 1) | (i & 1);
    const int mj = (j & ~15) | (((j >> 1) & 1) << 3) | (((j & 15) >> 2) << 1) | (j & 1);
    g_Qhi[mi * 128 + mj] = __float2half_rn(s);
}

// ---------------------------------------------------------------------------
__device__ __forceinline__ unsigned su32(const void* p)
{
    return (unsigned)__cvta_generic_to_shared(p);
}
__device__ __forceinline__ void ldsm4(unsigned r[4], unsigned a)
{
    asm volatile("ldmatrix.sync.aligned.m8n8.x4.shared.b16 {%0,%1,%2,%3}, [%4];\n"
                 : "=r"(r[0]), "=r"(r[1]), "=r"(r[2]), "=r"(r[3]) : "r"(a));
}
__device__ __forceinline__ void ldsm4t(unsigned r[4], unsigned a)
{
    asm volatile("ldmatrix.sync.aligned.m8n8.x4.trans.shared.b16 {%0,%1,%2,%3}, [%4];\n"
                 : "=r"(r[0]), "=r"(r[1]), "=r"(r[2]), "=r"(r[3]) : "r"(a));
}
__device__ __forceinline__ void mma16816(float c[4],
    unsigned a0, unsigned a1, unsigned a2, unsigned a3, unsigned b0, unsigned b1)
{
    asm volatile("mma.sync.aligned.m16n8k16.row.col.f32.f16.f16.f32 "
                 "{%0,%1,%2,%3}, {%4,%5,%6,%7}, {%8,%9}, {%0,%1,%2,%3};\n"
                 : "+f"(c[0]), "+f"(c[1]), "+f"(c[2]), "+f"(c[3])
                 : "r"(a0), "r"(a1), "r"(a2), "r"(a3), "r"(b0), "r"(b1));
}
__device__ __forceinline__ unsigned h2p(float a, float b)
{
    __half2 h = __floats2half2_rn(a, b);
    return *reinterpret_cast<unsigned*>(&h);
}

// ---------------------------------------------------------------------------
// Main kernel: 256 rows/CTA, 8 warps x 32 rows, 2 CTAs/SM.
// GEMM1 runs in two RoPE-closed n-halves ({0,1,4,5} / {2,3,6,7}) so the
// accumulator half (64f) + packed fh fit 128 regs at m=32; A is re-read
// (L2-hot) for the second half.  GEMM2 runs in four np-quarters with
// interleaved stores.  LDSM traffic per row is HALF of the m=16 kernel.
// ---------------------------------------------------------------------------
__global__ __launch_bounds__(256, 2)
void rnrope_main(const float* __restrict__ qg, const float* __restrict__ kg,
                 const float* __restrict__ cosg, const float* __restrict__ sing,
                 float* __restrict__ out)
{
    __shared__ __align__(16) __half sQ[128 * QS];    /* 34816 B */

    const int tid = threadIdx.x;
    for (int i = tid; i < 128 * 16; i += 256) {
        const int row = i >> 4;
        const int ch  = (i & 15) * 8;
        *(uint4*)&sQ[row * QS + ch] = *(const uint4*)&g_Qhi[row * 128 + ch];
    }
    __syncthreads();

    const int warp = tid >> 5, lane = tid & 31;
    const int u = lane & 3, g = lane >> 2;

    const int base  = blockIdx.x * 256;                /* 2048 blocks */
    const int local = (base < NT) ? base : base - NT;
    const float* x  = (base < NT) ? qg : kg;

    const float* A0 = x + (size_t)(local + warp * 32 + g) * 128;

    const int csr = ((local >> 17) << 13) + (local & 8191) + warp * 32 + g;
    const float* C0 = cosg + (size_t)csr * 128;
    const float* S0 = sing + (size_t)csr * 128;

    const int lbo = (((lane >> 4) << 3) + (lane & 7)) * QS + (((lane >> 3) & 1) << 3);

    unsigned fh0[16][2], fh1[16][2];

    // ================= GEMM1 + RoPE in two n-halves =================
#pragma unroll
    for (int h = 0; h < 2; h++) {
        float acc0[8][4], acc1[8][4];
#pragma unroll
        for (int n = 0; n < 8; n++)
#pragma unroll
            for (int i = 0; i < 4; i++) { acc0[n][i] = 0.f; acc1[n][i] = 0.f; }

#pragma unroll
        for (int kt = 0; kt < 8; kt++) {
            const int co = kt * 16 + 4 * u;
            const float4 r0 = *(const float4*)&A0[co];
            const float4 r1 = *(const float4*)&A0[co + 1024];
            const float4 r2 = *(const float4*)&A0[co + 2048];
            const float4 r3 = *(const float4*)&A0[co + 3072];
            const unsigned a00 = h2p(r0.x, r0.y), a01 = h2p(r1.x, r1.y);
            const unsigned a02 = h2p(r0.z, r0.w), a03 = h2p(r1.z, r1.w);
            const unsigned a10 = h2p(r2.x, r2.y), a11 = h2p(r3.x, r3.y);
            const unsigned a12 = h2p(r2.z, r2.w), a13 = h2p(r3.z, r3.w);
#pragma unroll
            for (int li = 0; li < 4; li++) {
                const int np = ((li < 2) ? li : li + 2) + h * 2;
                unsigned bh[4];
                ldsm4(bh, su32(sQ + np * (16 * QS) + kt * 16 + lbo));
                mma16816(acc0[2 * li],     a00, a01, a02, a03, bh[0], bh[1]);
                mma16816(acc0[2 * li + 1], a00, a01, a02, a03, bh[2], bh[3]);
                mma16816(acc1[2 * li],     a10, a11, a12, a13, bh[0], bh[1]);
                mma16816(acc1[2 * li + 1], a10, a11, a12, a13, bh[2], bh[3]);
            }
        }

        // RoPE half: local subtile t pairs with t+4 (np ↔ np+4 == e ↔ e+64)
        // m-tile 0 (rows g, g+8)
#pragma unroll
        for (int li = 0; li < 2; li++) {
            const int co = (li + h * 2) * 16 + 4 * u;
            const float4 cA = *(const float4*)&C0[co];
            const float4 cB = *(const float4*)&C0[co + 1024];
            const float4 sA = *(const float4*)&S0[co];
            const float4 sB = *(const float4*)&S0[co + 1024];
#pragma unroll
            for (int j = 0; j < 2; j++) {
                const int t = 2 * li + j, tp = t + 4;
                const float c0 = j ? cA.z : cA.x, c1 = j ? cA.w : cA.y;
                const float c2 = j ? cB.z : cB.x, c3 = j ? cB.w : cB.y;
                const float s0 = j ? sA.z : sA.x, s1 = j ? sA.w : sA.y;
                const float s2 = j ? sB.z : sB.x, s3 = j ? sB.w : sB.y;
                const float t0 = acc0[t][0], t1 = acc0[t][1];
                const float t2 = acc0[t][2], t3 = acc0[t][3];
                acc0[t][0]  = t0 * c0 - acc0[tp][0] * s0;
                acc0[t][1]  = t1 * c1 - acc0[tp][1] * s1;
                acc0[t][2]  = t2 * c2 - acc0[tp][2] * s2;
                acc0[t][3]  = t3 * c3 - acc0[tp][3] * s3;
                acc0[tp][0] = acc0[tp][0] * c0 + t0 * s0;
                acc0[tp][1] = acc0[tp][1] * c1 + t1 * s1;
                acc0[tp][2] = acc0[tp][2] * c2 + t2 * s2;
                acc0[tp][3] = acc0[tp][3] * c3 + t3 * s3;
            }
        }
        // m-tile 1 (rows g+16, g+24)
#pragma unroll
        for (int li = 0; li < 2; li++) {
            const int co = (li + h * 2) * 16 + 4 * u;
            const float4 cA = *(const float4*)&C0[co + 2048];
            const float4 cB = *(const float4*)&C0[co + 3072];
            const float4 sA = *(const float4*)&S0[co + 2048];
            const float4 sB = *(const float4*)&S0[co + 3072];
#pragma unroll
            for (int j = 0; j < 2; j++) {
                const int t = 2 * li + j, tp = t + 4;
                const float c0 = j ? cA.z : cA.x, c1 = j ? cA.w : cA.y;
                const float c2 = j ? cB.z : cB.x, c3 = j ? cB.w : cB.y;
                const float s0 = j ? sA.z : sA.x, s1 = j ? sA.w : sA.y;
                const float s2 = j ? sB.z : sB.x, s3 = j ? sB.w : sB.y;
                const float t0 = acc1[t][0], t1 = acc1[t][1];
                const float t2 = acc1[t][2], t3 = acc1[t][3];
                acc1[t][0]  = t0 * c0 - acc1[tp][0] * s0;
                acc1[t][1]  = t1 * c1 - acc1[tp][1] * s1;
                acc1[t][2]  = t2 * c2 - acc1[tp][2] * s2;
                acc1[t][3]  = t3 * c3 - acc1[tp][3] * s3;
                acc1[tp][0] = acc1[tp][0] * c0 + t0 * s0;
                acc1[tp][1] = acc1[tp][1] * c1 + t1 * s1;
                acc1[tp][2] = acc1[tp][2] * c2 + t2 * s2;
                acc1[tp][3] = acc1[tp][3] * c3 + t3 * s3;
            }
        }

        // pack rotated half into fh at the GLOBAL subtile index (= GEMM2 k slot)
#pragma unroll
        for (int li = 0; li < 4; li++) {
            const int npg = ((li < 2) ? li : li + 2) + h * 2;
#pragma unroll
            for (int j = 0; j < 2; j++) {
                fh0[2 * npg + j][0] = h2p(acc0[2 * li + j][0], acc0[2 * li + j][1]);
                fh0[2 * npg + j][1] = h2p(acc0[2 * li + j][2], acc0[2 * li + j][3]);
                fh1[2 * npg + j][0] = h2p(acc1[2 * li + j][0], acc1[2 * li + j][1]);
                fh1[2 * npg + j][1] = h2p(acc1[2 * li + j][2], acc1[2 * li + j][3]);
            }
        }
    }

    // ================= GEMM2 in four np-quarters =================
    float* O0 = out + (size_t)(base + warp * 32 + g) * 128;
#pragma unroll
    for (int qn = 0; qn < 4; qn++) {
        float o0[4][4], o1[4][4];
#pragma unroll
        for (int n = 0; n < 4; n++)
#pragma unroll
            for (int i = 0; i < 4; i++) { o0[n][i] = 0.f; o1[n][i] = 0.f; }

#pragma unroll
        for (int kt = 0; kt < 8; kt++) {
            const unsigned a00 = fh0[2 * kt][0],     a01 = fh0[2 * kt][1];
            const unsigned a02 = fh0[2 * kt + 1][0], a03 = fh0[2 * kt + 1][1];
            const unsigned a10 = fh1[2 * kt][0],     a11 = fh1[2 * kt][1];
            const unsigned a12 = fh1[2 * kt + 1][0], a13 = fh1[2 * kt + 1][1];
#pragma unroll
            for (int npq = 0; npq < 2; npq++) {
                const int np = 2 * qn + npq;
                unsigned bh[4];
                ldsm4t(bh, su32(sQ + kt * 16 * QS + np * 16 + lbo));
                mma16816(o0[2 * npq],     a00, a01, a02, a03, bh[0], bh[2]);
                mma16816(o0[2 * npq + 1], a00, a01, a02, a03, bh[1], bh[3]);
                mma16816(o1[2 * npq],     a10, a11, a12, a13, bh[0], bh[2]);
                mma16816(o1[2 * npq + 1], a10, a11, a12, a13, bh[1], bh[3]);
            }
        }
        // store this quarter (true col 16np+4u.. contiguous float4)
#pragma unroll
        for (int npq = 0; npq < 2; npq++) {
            const int np = 2 * qn + npq;
            const int col = np * 16 + 4 * u;
            *(float4*)&O0[col] =
                make_float4(o0[2*npq][0], o0[2*npq][1], o0[2*npq+1][0], o0[2*npq+1][1]);
            *(float4*)&O0[col + 1024] =
                make_float4(o0[2*npq][2], o0[2*npq][3], o0[2*npq+1][2], o0[2*npq+1][3]);
            *(float4*)&O0[col + 2048] =
                make_float4(o1[2*npq][0], o1[2*npq][1], o1[2*npq+1][0], o1[2*npq+1][1]);
            *(float4*)&O0[col + 3072] =
                make_float4(o1[2*npq][2], o1[2*npq][3], o1[2*npq+1][2], o1[2*npq+1][3]);
        }
    }
}

// ---------------------------------------------------------------------------
extern "C" void kernel_launch(void* const* d_in, const int* in_sizes, int n_in,
                              void* d_out, int out_size)
{
    (void)in_sizes; (void)n_in; (void)out_size;
    const float* q    = (const float*)d_in[0];
    const float* k    = (const float*)d_in[1];
    const float* vs   = (const float*)d_in[2];
    const float* cosg = (const float*)d_in[3];
    const float* sing = (const float*)d_in[4];
    float* out = (float*)d_out;

    build_p_kernel<<<32, 128>>>(vs);
    combine_q_kernel<<<128, 128>>>();
    rnrope_main<<<2048, 256>>>(q, k, cosg, sing, out);
}

// round 17
// speedup vs baseline: 1.5058x; 1.5058x over previous
#include <cuda_runtime.h>
#include <cuda_fp16.h>

#define NT  262144          /* B*H*S rows per tensor */
#define QS  136             /* smem row stride in halves */

__device__ __align__(16) float  g_P[2][16384];   /* 32-reflector partial products */
__device__ __align__(16) __half g_Qhi[16384];    /* em/dm-permuted Q */

// ---------------------------------------------------------------------------
// Stage 1: two parallel 32-reflector partial products.
// ---------------------------------------------------------------------------
__global__ void build_p_kernel(const float* __restrict__ vs)
{
    __shared__ float svs[32 * 128];
    __shared__ float sinv[32];
    const int t = threadIdx.x;
    const int chunk = blockIdx.x >> 4;
    const float* vsrc = vs + chunk * 32 * 128;
    for (int i = t; i < 32 * 128; i += 128) svs[i] = vsrc[i];
    __syncthreads();
    if (t < 32) {
        float nn = 0.f;
#pragma unroll 8
        for (int i = 0; i < 128; i += 4) {
            const float4 v = *(const float4*)&svs[t * 128 + i];
            nn += v.x * v.x + v.y * v.y + v.z * v.z + v.w * v.w;
        }
        sinv[t] = 2.0f / (nn + 1e-8f);
    }
    __syncthreads();

    const int col = (blockIdx.x & 15) * 8 + (t >> 4);
    const int ip  = t & 15;
    float qc[8];
#pragma unroll
    for (int j = 0; j < 8; j++) qc[j] = (ip * 8 + j == col) ? 1.0f : 0.0f;

    for (int r = 0; r < 32; r++) {
        const float* v = &svs[r * 128 + ip * 8];
        float w = 0.f;
#pragma unroll
        for (int j = 0; j < 8; j++) w += v[j] * qc[j];
#pragma unroll
        for (int off = 8; off; off >>= 1) w += __shfl_xor_sync(0xffffffffu, w, off);
        const float sw = sinv[r] * w;
#pragma unroll
        for (int j = 0; j < 8; j++) qc[j] -= sw * v[j];
    }
#pragma unroll
    for (int j = 0; j < 8; j++) g_P[chunk][(ip * 8 + j) * 128 + col] = qc[j];
}

// ---------------------------------------------------------------------------
// Stage 2: Q = P1 * P0 -> fp16, both dims within-16 permuted.
// ---------------------------------------------------------------------------
__global__ void combine_q_kernel()
{
    __shared__ float rowa[128];
    const int i = blockIdx.x, j = threadIdx.x;
    rowa[j] = g_P[1][i * 128 + j];
    __syncthreads();
    float s = 0.f;
#pragma unroll 8
    for (int e = 0; e < 128; e++) s += rowa[e] * g_P[0][e * 128 + j];
    const int mi = (i & ~15) | (((i >> 1) & 1) << 3) | (((i & 15) >> 2) << 1) | (i & 1);
    const int mj = (j & ~15) | (((j >> 1) & 1) << 3) | (((j & 15) >> 2) << 1) | (j & 1);
    g_Qhi[mi * 128 + mj] = __float2half_rn(s);
}

// ---------------------------------------------------------------------------
__device__ __forceinline__ unsigned su32(const void* p)
{
    return (unsigned)__cvta_generic_to_shared(p);
}
__device__ __forceinline__ void ldsm4(unsigned r[4], unsigned a)
{
    asm volatile("ldmatrix.sync.aligned.m8n8.x4.shared.b16 {%0,%1,%2,%3}, [%4];\n"
                 : "=r"(r[0]), "=r"(r[1]), "=r"(r[2]), "=r"(r[3]) : "r"(a));
}
__device__ __forceinline__ void ldsm4t(unsigned r[4], unsigned a)
{
    asm volatile("ldmatrix.sync.aligned.m8n8.x4.trans.shared.b16 {%0,%1,%2,%3}, [%4];\n"
                 : "=r"(r[0]), "=r"(r[1]), "=r"(r[2]), "=r"(r[3]) : "r"(a));
}
__device__ __forceinline__ void mma16816(float c[4],
    unsigned a0, unsigned a1, unsigned a2, unsigned a3, unsigned b0, unsigned b1)
{
    asm volatile("mma.sync.aligned.m16n8k16.row.col.f32.f16.f16.f32 "
                 "{%0,%1,%2,%3}, {%4,%5,%6,%7}, {%8,%9}, {%0,%1,%2,%3};\n"
                 : "+f"(c[0]), "+f"(c[1]), "+f"(c[2]), "+f"(c[3])
                 : "r"(a0), "r"(a1), "r"(a2), "r"(a3), "r"(b0), "r"(b1));
}
__device__ __forceinline__ unsigned h2p(float a, float b)
{
    __half2 h = __floats2half2_rn(a, b);
    return *reinterpret_cast<unsigned*>(&h);
}

// ---------------------------------------------------------------------------
// Main kernel: 128 rows/CTA, 8 warps x 16 rows, 2 CTAs/SM (R12 tiling).
// Reordered for schedulability: A preloaded+converted up front (MLP=16),
// GEMM1 in np-pairs (np, np+4) with RoPE+pack fused (acc live = 16f),
// GEMM2 np-outer with interleaved stores (o live = 8f). Peak ~119 regs.
// ---------------------------------------------------------------------------
__global__ __launch_bounds__(256, 2)
void rnrope_main(const float* __restrict__ qg, const float* __restrict__ kg,
                 const float* __restrict__ cosg, const float* __restrict__ sing,
                 float* __restrict__ out)
{
    __shared__ __align__(16) __half sQ[128 * QS];    /* 34816 B */

    const int tid = threadIdx.x;
    for (int i = tid; i < 128 * 16; i += 256) {
        const int row = i >> 4;
        const int ch  = (i & 15) * 8;
        *(uint4*)&sQ[row * QS + ch] = *(const uint4*)&g_Qhi[row * 128 + ch];
    }
    __syncthreads();

    const int warp = tid >> 5, lane = tid & 31;
    const int u = lane & 3, g = lane >> 2;

    const int base  = blockIdx.x * 128;                /* 4096 blocks */
    const int local = (base < NT) ? base : base - NT;
    const float* x  = (base < NT) ? qg : kg;

    const float* A0 = x + (size_t)(local + warp * 16 + g) * 128;
    const float* A1 = A0 + 8 * 128;

    const int csr = ((local >> 17) << 13) + (local & 8191) + warp * 16 + g;
    const float* C0 = cosg + (size_t)csr * 128;
    const float* C1 = C0 + 8 * 128;
    const float* S0 = sing + (size_t)csr * 128;
    const float* S1 = S0 + 8 * 128;

    const int lbo = (((lane >> 4) << 3) + (lane & 7)) * QS + (((lane >> 3) & 1) << 3);

    // ---- preload + convert ALL A fragments (16 back-to-back LDG.128) ----
    unsigned af[8][4];
#pragma unroll
    for (int kt = 0; kt < 8; kt++) {
        const int co = kt * 16 + 4 * u;
        const float4 r0 = *(const float4*)&A0[co];
        const float4 r1 = *(const float4*)&A1[co];
        af[kt][0] = h2p(r0.x, r0.y);
        af[kt][1] = h2p(r1.x, r1.y);
        af[kt][2] = h2p(r0.z, r0.w);
        af[kt][3] = h2p(r1.z, r1.w);
    }

    // ---- GEMM1 + RoPE + pack, one RoPE-closed np-pair at a time ----
    unsigned fh[16][2];
#pragma unroll
    for (int np = 0; np < 4; np++) {
        const int co = np * 16 + 4 * u;
        const float4 cA = *(const float4*)&C0[co];
        const float4 cB = *(const float4*)&C1[co];
        const float4 sA = *(const float4*)&S0[co];
        const float4 sB = *(const float4*)&S1[co];

        float accA[2][4], accB[2][4];
#pragma unroll
        for (int j = 0; j < 2; j++)
#pragma unroll
            for (int i = 0; i < 4; i++) { accA[j][i] = 0.f; accB[j][i] = 0.f; }

#pragma unroll
        for (int kt = 0; kt < 8; kt++) {
            unsigned bh[4], bh2[4];
            ldsm4(bh,  su32(sQ + np * (16 * QS)       + kt * 16 + lbo));
            ldsm4(bh2, su32(sQ + (np + 4) * (16 * QS) + kt * 16 + lbo));
            mma16816(accA[0], af[kt][0], af[kt][1], af[kt][2], af[kt][3], bh[0],  bh[1]);
            mma16816(accA[1], af[kt][0], af[kt][1], af[kt][2], af[kt][3], bh[2],  bh[3]);
            mma16816(accB[0], af[kt][0], af[kt][1], af[kt][2], af[kt][3], bh2[0], bh2[1]);
            mma16816(accB[1], af[kt][0], af[kt][1], af[kt][2], af[kt][3], bh2[2], bh2[3]);
        }

        // RoPE: subtile (2np+j) pairs with (2(np+4)+j); cos/sin shared (e vs e+64)
#pragma unroll
        for (int j = 0; j < 2; j++) {
            const float c0 = j ? cA.z : cA.x, c1 = j ? cA.w : cA.y;
            const float c2 = j ? cB.z : cB.x, c3 = j ? cB.w : cB.y;
            const float s0 = j ? sA.z : sA.x, s1 = j ? sA.w : sA.y;
            const float s2 = j ? sB.z : sB.x, s3 = j ? sB.w : sB.y;
            const float t0 = accA[j][0], t1 = accA[j][1];
            const float t2 = accA[j][2], t3 = accA[j][3];
            const float z0 = t0 * c0 - accB[j][0] * s0;
            const float z1 = t1 * c1 - accB[j][1] * s1;
            const float z2 = t2 * c2 - accB[j][2] * s2;
            const float z3 = t3 * c3 - accB[j][3] * s3;
            const float w0 = accB[j][0] * c0 + t0 * s0;
            const float w1 = accB[j][1] * c1 + t1 * s1;
            const float w2 = accB[j][2] * c2 + t2 * s2;
            const float w3 = accB[j][3] * c3 + t3 * s3;
            fh[2 * np + j][0]       = h2p(z0, z1);
            fh[2 * np + j][1]       = h2p(z2, z3);
            fh[2 * (np + 4) + j][0] = h2p(w0, w1);
            fh[2 * (np + 4) + j][1] = h2p(w2, w3);
        }
    }

    // ---- GEMM2: np-outer, kt-inner, store per np (o live = 8f) ----
    float* O0 = out + (size_t)(base + warp * 16 + g) * 128;
    float* O1 = O0 + 8 * 128;
#pragma unroll
    for (int np = 0; np < 8; np++) {
        float o0[4], o1[4];
#pragma unroll
        for (int i = 0; i < 4; i++) { o0[i] = 0.f; o1[i] = 0.f; }
#pragma unroll
        for (int kt = 0; kt < 8; kt++) {
            unsigned bh[4];
            ldsm4t(bh, su32(sQ + kt * 16 * QS + np * 16 + lbo));
            mma16816(o0, fh[2 * kt][0], fh[2 * kt][1],
                         fh[2 * kt + 1][0], fh[2 * kt + 1][1], bh[0], bh[2]);
            mma16816(o1, fh[2 * kt][0], fh[2 * kt][1],
                         fh[2 * kt + 1][0], fh[2 * kt + 1][1], bh[1], bh[3]);
        }
        const int col = np * 16 + 4 * u;
        *(float4*)&O0[col] = make_float4(o0[0], o0[1], o1[0], o1[1]);
        *(float4*)&O1[col] = make_float4(o0[2], o0[3], o1[2], o1[3]);
    }
}

// ---------------------------------------------------------------------------
extern "C" void kernel_launch(void* const* d_in, const int* in_sizes, int n_in,
                              void* d_out, int out_size)
{
    (void)in_sizes; (void)n_in; (void)out_size;
    const float* q    = (const float*)d_in[0];
    const float* k    = (const float*)d_in[1];
    const float* vs   = (const float*)d_in[2];
    const float* cosg = (const float*)d_in[3];
    const float* sing = (const float*)d_in[4];
    float* out = (float*)d_out;

    build_p_kernel<<<32, 128>>>(vs);
    combine_q_kernel<<<128, 128>>>();
    rnrope_main<<<4096, 256>>>(q, k, cosg, sing, out);
}